// round 9
// baseline (speedup 1.0000x reference)
#include <cuda_runtime.h>
#include <cstdint>
#include <cstddef>

// Problem dims
#define NN 16384
#define DD 64
#define MTILE 128
#define KTILE 128
#define NSTAGES 2
#define NKT (NN / KTILE)            // 128 k-tiles

// Smem: padded row stride 132 floats (528B; 16B-aligned, stride%32 banks == 4 -> LDSM conflict-free)
#define RS 132
#define ROW_B (RS * 4)                        // 528
#define A_TILE_B (MTILE * ROW_B)              // 67584
#define B_TILE_B (DD * ROW_B)                 // 33792
#define STAGE_B (A_TILE_B + B_TILE_B)         // 101376
#define CTRL_B 1024
#define SMEM_TOTAL (CTRL_B + NSTAGES * STAGE_B)  // 203776
#define TX_BYTES ((MTILE + DD) * 512)         // 98304 bytes of payload per stage

// Scratch: Y^T = (X @ W_agg)^T, [DD][NN] fp32 (tf32-rounded, truncation-compensated)
__device__ float g_Yt[(size_t)DD * NN];

// ---------------- helpers ----------------
__device__ __forceinline__ uint32_t smem_u32(const void* p) {
    uint32_t a;
    asm("{ .reg .u64 t; cvta.to.shared.u64 t, %1; cvt.u32.u64 %0, t; }" : "=r"(a) : "l"(p));
    return a;
}

// 1D bulk async copy gmem->smem with mbarrier transaction accounting (sm_90 baseline)
__device__ __forceinline__ void bulk_cp(uint32_t dst, const void* src, uint32_t bytes,
                                        uint32_t mbar) {
    asm volatile(
        "cp.async.bulk.shared::cta.global.mbarrier::complete_tx::bytes [%0], [%1], %2, [%3];"
        :: "r"(dst), "l"(src), "r"(bytes), "r"(mbar) : "memory");
}
#define MBAR_INIT(a, c) \
    asm volatile("mbarrier.init.shared.b64 [%0], %1;" :: "r"(a), "r"(c) : "memory")
#define MBAR_EXPECT(a, b) \
    asm volatile("mbarrier.arrive.expect_tx.shared.b64 _, [%0], %1;" :: "r"(a), "r"(b) : "memory")

__device__ __forceinline__ void mbar_wait(uint32_t mbar, uint32_t parity) {
    asm volatile(
        "{\n\t.reg .pred P;\n"
        "W_%=:\n\t"
        "mbarrier.try_wait.parity.acquire.cta.shared::cta.b64 P, [%0], %1, 0x989680;\n\t"
        "@P bra.uni D_%=;\n\t"
        "bra.uni W_%=;\n"
        "D_%=:\n\t}"
        :: "r"(mbar), "r"(parity) : "memory");
}

__device__ __forceinline__ void ldsm_x4(uint32_t r[4], uint32_t addr) {
    asm volatile("ldmatrix.sync.aligned.m8n8.x4.shared.b16 {%0,%1,%2,%3}, [%4];"
                 : "=r"(r[0]), "=r"(r[1]), "=r"(r[2]), "=r"(r[3]) : "r"(addr));
}

// tf32 mma.sync m16n8k8, row.col, f32 accumulate
__device__ __forceinline__ void mma_tf32(float d[4], const uint32_t a[4],
                                         uint32_t b0, uint32_t b1) {
    asm volatile(
        "mma.sync.aligned.m16n8k8.row.col.f32.tf32.tf32.f32 "
        "{%0,%1,%2,%3}, {%4,%5,%6,%7}, {%8,%9}, {%0,%1,%2,%3};"
        : "+f"(d[0]), "+f"(d[1]), "+f"(d[2]), "+f"(d[3])
        : "r"(a[0]), "r"(a[1]), "r"(a[2]), "r"(a[3]), "r"(b0), "r"(b1));
}

// ---------------- Kernel 1: Yt = round_tf32( comp * (X @ W_agg)^T ) ----------------
__global__ void __launch_bounds__(128) y_kernel(const float* __restrict__ X,
                                                const float* __restrict__ Wg) {
    __shared__ float Ws[DD * DD];
    const int t = threadIdx.x;
    for (int i = t; i < DD * DD; i += 128) Ws[i] = Wg[i];
    __syncthreads();

    const int row = blockIdx.x * 128 + t;
    float4 xv[16];
    const float4* Xr = (const float4*)(X + (size_t)row * DD);
#pragma unroll
    for (int i = 0; i < 16; ++i) xv[i] = Xr[i];
    const float* xs = (const float*)xv;

    const float comp = 1.00035f;   // compensate A-operand tf32 truncation bias

#pragma unroll
    for (int p = 0; p < 4; ++p) {
        float acc[16];
#pragma unroll
        for (int d = 0; d < 16; ++d) acc[d] = 0.f;
#pragma unroll
        for (int j = 0; j < 64; ++j) {
            const float xj = xs[j];
            const float4* wr = (const float4*)&Ws[j * 64 + p * 16];
            float4 w0 = wr[0], w1 = wr[1], w2 = wr[2], w3 = wr[3];
            acc[0]  += xj * w0.x; acc[1]  += xj * w0.y; acc[2]  += xj * w0.z; acc[3]  += xj * w0.w;
            acc[4]  += xj * w1.x; acc[5]  += xj * w1.y; acc[6]  += xj * w1.z; acc[7]  += xj * w1.w;
            acc[8]  += xj * w2.x; acc[9]  += xj * w2.y; acc[10] += xj * w2.z; acc[11] += xj * w2.w;
            acc[12] += xj * w3.x; acc[13] += xj * w3.y; acc[14] += xj * w3.z; acc[15] += xj * w3.w;
        }
#pragma unroll
        for (int d = 0; d < 16; ++d) {
            float v = acc[d] * comp;
            uint32_t b;
            asm("cvt.rna.tf32.f32 %0, %1;" : "=r"(b) : "f"(v));
            g_Yt[(size_t)(p * 16 + d) * NN + row] = __uint_as_float(b);
        }
    }
}

// ---------------- Kernel 2: main GEMM + fused epilogue ----------------
// Stage fill via cp.async.bulk: 192 ops (one 512B row each) spread over threads 0..191.
__device__ __forceinline__ void fill_stage(uint32_t sb, int slot, int kt,
                                           const float* __restrict__ A,
                                           int mbase, int tid) {
    const uint32_t st = sb + CTRL_B + slot * STAGE_B;
    const uint32_t mbar = sb + 8 * slot;
    if (tid == 0) MBAR_EXPECT(mbar, TX_BYTES);
    if (tid < MTILE) {
        // A row `tid`
        const char* src = (const char*)A + (size_t)(mbase + tid) * (NN * 4)
                          + (size_t)kt * (KTILE * 4);
        bulk_cp(st + tid * ROW_B, src, KTILE * 4, mbar);
    } else if (tid < MTILE + DD) {
        // B row `tid - MTILE`
        const int r = tid - MTILE;
        const char* src = (const char*)g_Yt + (size_t)r * (NN * 4)
                          + (size_t)kt * (KTILE * 4);
        bulk_cp(st + A_TILE_B + r * ROW_B, src, KTILE * 4, mbar);
    }
}

__global__ void __launch_bounds__(256, 1) gcn_main(const float* __restrict__ A,
                                                   const float* __restrict__ X,
                                                   const float* __restrict__ wv,
                                                   float* __restrict__ out) {
    extern __shared__ __align__(1024) float smem[];
    const uint32_t sb = smem_u32(smem);
    const int tid = threadIdx.x;
    const int lane = tid & 31;
    const int wid = tid >> 5;
    const int wm = wid & 3;        // 4 m-groups of 32 rows
    const int wn = wid >> 2;       // 2 n-groups of 32 cols
    const int mbase = blockIdx.x * MTILE;

    if (tid == 0) {
        MBAR_INIT(sb + 0, 1);
        MBAR_INIT(sb + 8, 1);
    }
    __syncthreads();

    // Accumulators: 2 m-steps x 4 n-steps x 4 regs
    float acc[2][4][4];
#pragma unroll
    for (int ms = 0; ms < 2; ++ms)
#pragma unroll
        for (int ns = 0; ns < 4; ++ns)
#pragma unroll
            for (int r = 0; r < 4; ++r) acc[ms][ns][r] = 0.f;

    // ldmatrix per-thread base addresses (byte offsets), layout identical to R3/R4 (validated)
    const uint32_t a_addr0 = sb + CTRL_B +
        4u * ((wm * 32 + (lane & 15)) * RS + (lane >> 4) * 4);
    const uint32_t b_addr0 = sb + CTRL_B + A_TILE_B +
        4u * ((wn * 32 + (lane & 7) + ((lane >> 4) << 3)) * RS + ((lane >> 3) & 1) * 4);

    // Prologue: fill stage 0 with k-tile 0
    fill_stage(sb, 0, 0, A, mbase, tid);

    int slot = 0;
    for (int kt = 0; kt < NKT; ++kt) {
        // Stage `slot` carries k-tile kt; parity flips every other use of the same slot
        mbar_wait(sb + 8 * slot, (kt >> 1) & 1);
        __syncthreads();   // all warps done reading stage slot^1 (tile kt-1) -> safe to refill

        if (kt + 1 < NKT) fill_stage(sb, slot ^ 1, kt + 1, A, mbase, tid);

        const uint32_t sa = a_addr0 + slot * STAGE_B;
        const uint32_t sbb = b_addr0 + slot * STAGE_B;

        // Double-buffered fragments: LDSM for ks+1 issues before HMMAs for ks
        uint32_t af[2][2][4], bf[2][2][4];
        ldsm_x4(af[0][0], sa);
        ldsm_x4(af[0][1], sa + 16 * ROW_B);
        ldsm_x4(bf[0][0], sbb);
        ldsm_x4(bf[0][1], sbb + 16 * ROW_B);
#pragma unroll
        for (int ks = 0; ks < KTILE / 8; ++ks) {
            const int cur = ks & 1;
            const int nxt = cur ^ 1;
            if (ks + 1 < KTILE / 8) {
                ldsm_x4(af[nxt][0], sa + (ks + 1) * 32);
                ldsm_x4(af[nxt][1], sa + 16 * ROW_B + (ks + 1) * 32);
                ldsm_x4(bf[nxt][0], sbb + (ks + 1) * 32);
                ldsm_x4(bf[nxt][1], sbb + 16 * ROW_B + (ks + 1) * 32);
            }
#pragma unroll
            for (int ms = 0; ms < 2; ++ms) {
                mma_tf32(acc[ms][0], af[cur][ms], bf[cur][0][0], bf[cur][0][1]);
                mma_tf32(acc[ms][1], af[cur][ms], bf[cur][0][2], bf[cur][0][3]);
                mma_tf32(acc[ms][2], af[cur][ms], bf[cur][1][0], bf[cur][1][1]);
                mma_tf32(acc[ms][3], af[cur][ms], bf[cur][1][2], bf[cur][1][3]);
            }
        }
        slot ^= 1;
    }

    // Fused epilogue: out = w*relu(acc) + (1-w)*X, straight from registers
    const int l4 = lane >> 2;
    const int lm = lane & 3;
#pragma unroll
    for (int ms = 0; ms < 2; ++ms) {
        const int r0 = mbase + wm * 32 + ms * 16 + l4;
        const int r1 = r0 + 8;
        const float w0 = wv[r0], o0 = 1.0f - w0;
        const float w1 = wv[r1], o1 = 1.0f - w1;
#pragma unroll
        for (int ns = 0; ns < 4; ++ns) {
            const int col = wn * 32 + ns * 8 + lm * 2;
            const float2 x0 = *(const float2*)(X + (size_t)r0 * DD + col);
            const float2 x1 = *(const float2*)(X + (size_t)r1 * DD + col);
            float2 v0, v1;
            v0.x = w0 * fmaxf(acc[ms][ns][0], 0.f) + o0 * x0.x;
            v0.y = w0 * fmaxf(acc[ms][ns][1], 0.f) + o0 * x0.y;
            v1.x = w1 * fmaxf(acc[ms][ns][2], 0.f) + o1 * x1.x;
            v1.y = w1 * fmaxf(acc[ms][ns][3], 0.f) + o1 * x1.y;
            *(float2*)(out + (size_t)r0 * DD + col) = v0;
            *(float2*)(out + (size_t)r1 * DD + col) = v1;
        }
    }
}

// ---------------- launch ----------------
extern "C" void kernel_launch(void* const* d_in, const int* in_sizes, int n_in,
                              void* d_out, int out_size) {
    const float* X  = (const float*)d_in[0];
    const float* A  = (const float*)d_in[1];
    const float* wv = (const float*)d_in[2];
    const float* Wg = (const float*)d_in[3];
    float* out = (float*)d_out;

    cudaFuncSetAttribute(gcn_main, cudaFuncAttributeMaxDynamicSharedMemorySize, SMEM_TOTAL);

    y_kernel<<<NN / 128, 128>>>(X, Wg);
    gcn_main<<<NN / MTILE, 256, SMEM_TOTAL>>>(A, X, wv, out);
}

// round 10
// speedup vs baseline: 1.5680x; 1.5680x over previous
#include <cuda_runtime.h>
#include <cuda.h>
#include <cstdint>
#include <cstddef>

// Problem dims
#define NN 16384
#define DD 64
#define MTILE 128
#define KTILE 128
#define NKT (NN / KTILE)            // 128 k-tiles

// Smem stage: A tile 4 chunk-tiles of [128 rows x 128B] (SW128), B tile 4 of [64 x 128B]
#define A_TILE_B 65536
#define B_TILE_B 32768
#define STAGE_B (A_TILE_B + B_TILE_B)   // 98304
#define CTRL_B 1024
#define SMEM_TOTAL (CTRL_B + 2 * STAGE_B)   // 197632
#define TX_BYTES STAGE_B

// Scratch: Y^T = (X @ W_agg)^T, [DD][NN] fp32 (tf32-rounded, truncation-compensated)
__device__ float g_Yt[(size_t)DD * NN];

// ---------------- helpers ----------------
__device__ __forceinline__ uint32_t smem_u32(const void* p) {
    uint32_t a;
    asm("{ .reg .u64 t; cvta.to.shared.u64 t, %1; cvt.u32.u64 %0, t; }" : "=r"(a) : "l"(p));
    return a;
}
#define MBAR_INIT(a, c) \
    asm volatile("mbarrier.init.shared.b64 [%0], %1;" :: "r"(a), "r"(c) : "memory")
#define MBAR_EXPECT(a, b) \
    asm volatile("mbarrier.arrive.expect_tx.shared.b64 _, [%0], %1;" :: "r"(a), "r"(b) : "memory")

__device__ __forceinline__ void mbar_wait(uint32_t mbar, uint32_t parity) {
    asm volatile(
        "{\n\t.reg .pred P;\n"
        "W_%=:\n\t"
        "mbarrier.try_wait.parity.acquire.cta.shared::cta.b64 P, [%0], %1, 0x989680;\n\t"
        "@P bra.uni D_%=;\n\t"
        "bra.uni W_%=;\n"
        "D_%=:\n\t}"
        :: "r"(mbar), "r"(parity) : "memory");
}

__device__ __forceinline__ void tma3(uint32_t dst, const CUtensorMap* tm,
                                     int x, int y, int z, uint32_t mbar) {
    asm volatile(
        "cp.async.bulk.tensor.3d.shared::cta.global.tile.mbarrier::complete_tx::bytes "
        "[%0], [%1, {%2, %3, %4}], [%5];"
        :: "r"(dst), "l"(tm), "r"(x), "r"(y), "r"(z), "r"(mbar) : "memory");
}

__device__ __forceinline__ void ldsm_x4(uint32_t r[4], uint32_t addr) {
    asm volatile("ldmatrix.sync.aligned.m8n8.x4.shared.b16 {%0,%1,%2,%3}, [%4];"
                 : "=r"(r[0]), "=r"(r[1]), "=r"(r[2]), "=r"(r[3]) : "r"(addr));
}

// tf32 mma.sync m16n8k8, row.col, f32 accumulate
__device__ __forceinline__ void mma_tf32(float d[4], const uint32_t a[4],
                                         uint32_t b0, uint32_t b1) {
    asm volatile(
        "mma.sync.aligned.m16n8k8.row.col.f32.tf32.tf32.f32 "
        "{%0,%1,%2,%3}, {%4,%5,%6,%7}, {%8,%9}, {%0,%1,%2,%3};"
        : "+f"(d[0]), "+f"(d[1]), "+f"(d[2]), "+f"(d[3])
        : "r"(a[0]), "r"(a[1]), "r"(a[2]), "r"(a[3]), "r"(b0), "r"(b1));
}

// ---------------- Kernel 1: Yt = round_tf32( comp * (X @ W_agg)^T ) ----------------
__global__ void __launch_bounds__(128) y_kernel(const float* __restrict__ X,
                                                const float* __restrict__ Wg) {
    __shared__ float Ws[DD * DD];
    const int t = threadIdx.x;
    for (int i = t; i < DD * DD; i += 128) Ws[i] = Wg[i];
    __syncthreads();

    const int row = blockIdx.x * 128 + t;
    float4 xv[16];
    const float4* Xr = (const float4*)(X + (size_t)row * DD);
#pragma unroll
    for (int i = 0; i < 16; ++i) xv[i] = Xr[i];
    const float* xs = (const float*)xv;

    const float comp = 1.00035f;   // compensate A-operand tf32 truncation bias

#pragma unroll
    for (int p = 0; p < 4; ++p) {
        float acc[16];
#pragma unroll
        for (int d = 0; d < 16; ++d) acc[d] = 0.f;
#pragma unroll
        for (int j = 0; j < 64; ++j) {
            const float xj = xs[j];
            const float4* wr = (const float4*)&Ws[j * 64 + p * 16];
            float4 w0 = wr[0], w1 = wr[1], w2 = wr[2], w3 = wr[3];
            acc[0]  += xj * w0.x; acc[1]  += xj * w0.y; acc[2]  += xj * w0.z; acc[3]  += xj * w0.w;
            acc[4]  += xj * w1.x; acc[5]  += xj * w1.y; acc[6]  += xj * w1.z; acc[7]  += xj * w1.w;
            acc[8]  += xj * w2.x; acc[9]  += xj * w2.y; acc[10] += xj * w2.z; acc[11] += xj * w2.w;
            acc[12] += xj * w3.x; acc[13] += xj * w3.y; acc[14] += xj * w3.z; acc[15] += xj * w3.w;
        }
#pragma unroll
        for (int d = 0; d < 16; ++d) {
            float v = acc[d] * comp;
            uint32_t b;
            asm("cvt.rna.tf32.f32 %0, %1;" : "=r"(b) : "f"(v));
            g_Yt[(size_t)(p * 16 + d) * NN + row] = __uint_as_float(b);
        }
    }
}

// ---------------- Kernel 2: main GEMM (tensor-TMA fill) + fused epilogue ----------------
__device__ __forceinline__ void fill_stage(uint32_t sb, int slot, int kt,
                                           const CUtensorMap* tmA, const CUtensorMap* tmB,
                                           int mbase, int tid) {
    if (tid == 0) {
        const uint32_t mbar = sb + 8 * slot;
        const uint32_t st = sb + CTRL_B + slot * STAGE_B;
        MBAR_EXPECT(mbar, TX_BYTES);
        tma3(st, tmA, 0, mbase, kt * 4, mbar);              // A tile 128x128f
        tma3(st + A_TILE_B, tmB, 0, 0, kt * 4, mbar);       // B tile 64x128f
    }
}

__global__ void __launch_bounds__(256, 1) gcn_main(
    const __grid_constant__ CUtensorMap tmA,
    const __grid_constant__ CUtensorMap tmB,
    const float* __restrict__ X,
    const float* __restrict__ wv,
    float* __restrict__ out) {
    extern __shared__ __align__(1024) float smem[];
    const uint32_t sb = smem_u32(smem);
    const int tid = threadIdx.x;
    const int lane = tid & 31;
    const int wid = tid >> 5;
    const int wm = wid & 3;        // 4 m-groups of 32 rows
    const int wn = wid >> 2;       // 2 n-groups of 32 cols
    const int mbase = blockIdx.x * MTILE;

    if (tid == 0) {
        MBAR_INIT(sb + 0, 1);
        MBAR_INIT(sb + 8, 1);
    }
    __syncthreads();

    float acc[2][4][4];
#pragma unroll
    for (int ms = 0; ms < 2; ++ms)
#pragma unroll
        for (int ns = 0; ns < 4; ++ns)
#pragma unroll
            for (int r = 0; r < 4; ++r) acc[ms][ns][r] = 0.f;

    // Fragment addressing in SW128 chunk-tile layout.
    // A: 4 chunk-tiles of [128 rows x 32f]; row r, col c(byte) -> r*128 + (c ^ ((r&7)<<4))
    const uint32_t swx = (uint32_t)(lane & 7) << 4;            // swizzle XOR (rows & cols of both frags share it)
    const uint32_t aOff0 = (uint32_t)(wm * 32 + (lane & 15)) * 128;
    const uint32_t aCol0 = (uint32_t)((lane >> 4) << 4);       // 0 or 16
    const uint32_t bRow = (uint32_t)(wn * 32 + (lane & 7) + ((lane >> 4) << 3));
    const uint32_t bOff0 = bRow * 128;
    const uint32_t bCol0 = (uint32_t)(((lane >> 3) & 1) << 4);

    // Prologue: fill stage 0 with k-tile 0
    fill_stage(sb, 0, 0, &tmA, &tmB, mbase, tid);

    int slot = 0;
    for (int kt = 0; kt < NKT; ++kt) {
        mbar_wait(sb + 8 * slot, (kt >> 1) & 1);
        __syncthreads();   // all warps done reading stage slot^1 -> safe to refill

        if (kt + 1 < NKT) fill_stage(sb, slot ^ 1, kt + 1, &tmA, &tmB, mbase, tid);

        const uint32_t sA = sb + CTRL_B + slot * STAGE_B;
        const uint32_t sB = sA + A_TILE_B;

        // address generators (ks literal under full unroll -> constants fold)
        auto aAddr = [&](int ms, int ks) -> uint32_t {
            return sA + (uint32_t)((ks >> 2) * 16384) + aOff0 + (uint32_t)(ms * 2048)
                   + ((((uint32_t)((ks & 3) * 32)) | aCol0) ^ swx);
        };
        auto bAddr = [&](int half, int ks) -> uint32_t {
            return sB + (uint32_t)((ks >> 2) * 8192) + bOff0 + (uint32_t)(half * 2048)
                   + ((((uint32_t)((ks & 3) * 32)) | bCol0) ^ swx);
        };

        uint32_t af[2][2][4], bf[2][2][4];
        ldsm_x4(af[0][0], aAddr(0, 0));
        ldsm_x4(af[0][1], aAddr(1, 0));
        ldsm_x4(bf[0][0], bAddr(0, 0));
        ldsm_x4(bf[0][1], bAddr(1, 0));
#pragma unroll
        for (int ks = 0; ks < KTILE / 8; ++ks) {
            const int cur = ks & 1;
            const int nxt = cur ^ 1;
            if (ks + 1 < KTILE / 8) {
                ldsm_x4(af[nxt][0], aAddr(0, ks + 1));
                ldsm_x4(af[nxt][1], aAddr(1, ks + 1));
                ldsm_x4(bf[nxt][0], bAddr(0, ks + 1));
                ldsm_x4(bf[nxt][1], bAddr(1, ks + 1));
            }
#pragma unroll
            for (int ms = 0; ms < 2; ++ms) {
                mma_tf32(acc[ms][0], af[cur][ms], bf[cur][0][0], bf[cur][0][1]);
                mma_tf32(acc[ms][1], af[cur][ms], bf[cur][0][2], bf[cur][0][3]);
                mma_tf32(acc[ms][2], af[cur][ms], bf[cur][1][0], bf[cur][1][1]);
                mma_tf32(acc[ms][3], af[cur][ms], bf[cur][1][2], bf[cur][1][3]);
            }
        }
        slot ^= 1;
    }

    // Fused epilogue: out = w*relu(acc) + (1-w)*X, straight from registers
    const int l4 = lane >> 2;
    const int lm = lane & 3;
#pragma unroll
    for (int ms = 0; ms < 2; ++ms) {
        const int r0 = mbase + wm * 32 + ms * 16 + l4;
        const int r1 = r0 + 8;
        const float w0 = wv[r0], o0 = 1.0f - w0;
        const float w1 = wv[r1], o1 = 1.0f - w1;
#pragma unroll
        for (int ns = 0; ns < 4; ++ns) {
            const int col = wn * 32 + ns * 8 + lm * 2;
            const float2 x0 = *(const float2*)(X + (size_t)r0 * DD + col);
            const float2 x1 = *(const float2*)(X + (size_t)r1 * DD + col);
            float2 v0, v1;
            v0.x = w0 * fmaxf(acc[ms][ns][0], 0.f) + o0 * x0.x;
            v0.y = w0 * fmaxf(acc[ms][ns][1], 0.f) + o0 * x0.y;
            v1.x = w1 * fmaxf(acc[ms][ns][2], 0.f) + o1 * x1.x;
            v1.y = w1 * fmaxf(acc[ms][ns][3], 0.f) + o1 * x1.y;
            *(float2*)(out + (size_t)r0 * DD + col) = v0;
            *(float2*)(out + (size_t)r1 * DD + col) = v1;
        }
    }
}

// ---------------- launch ----------------
typedef CUresult (*EncodeFn)(CUtensorMap*, CUtensorMapDataType, cuuint32_t, void*,
                             const cuuint64_t*, const cuuint64_t*, const cuuint32_t*,
                             const cuuint32_t*, CUtensorMapInterleave, CUtensorMapSwizzle,
                             CUtensorMapL2promotion, CUtensorMapFloatOOBfill);

extern "C" void kernel_launch(void* const* d_in, const int* in_sizes, int n_in,
                              void* d_out, int out_size) {
    const float* X  = (const float*)d_in[0];
    const float* A  = (const float*)d_in[1];
    const float* wv = (const float*)d_in[2];
    const float* Wg = (const float*)d_in[3];
    float* out = (float*)d_out;

    // Resolve driver-API tensor-map encoder without linking libcuda
    void* fn = nullptr;
    cudaDriverEntryPointQueryResult qr;
    cudaGetDriverEntryPoint("cuTensorMapEncodeTiled", &fn, cudaEnableDefault, &qr);
    EncodeFn enc = (EncodeFn)fn;

    void* ytPtr = nullptr;
    cudaGetSymbolAddress(&ytPtr, g_Yt);

    // A as 3D: (32 floats, NN rows, NN/32 chunks); elem (x,y,z) at y*NN*4 + z*128 + x*4
    CUtensorMap tmA, tmB;
    {
        cuuint64_t dims[3] = {32, NN, NN / 32};
        cuuint64_t str[2]  = {(cuuint64_t)NN * 4, 128};
        cuuint32_t box[3]  = {32, MTILE, KTILE / 32};
        cuuint32_t es[3]   = {1, 1, 1};
        enc(&tmA, CU_TENSOR_MAP_DATA_TYPE_FLOAT32, 3, (void*)A, dims, str, box, es,
            CU_TENSOR_MAP_INTERLEAVE_NONE, CU_TENSOR_MAP_SWIZZLE_128B,
            CU_TENSOR_MAP_L2_PROMOTION_L2_128B, CU_TENSOR_MAP_FLOAT_OOB_FILL_NONE);
    }
    {
        cuuint64_t dims[3] = {32, DD, NN / 32};
        cuuint64_t str[2]  = {(cuuint64_t)NN * 4, 128};
        cuuint32_t box[3]  = {32, DD, KTILE / 32};
        cuuint32_t es[3]   = {1, 1, 1};
        enc(&tmB, CU_TENSOR_MAP_DATA_TYPE_FLOAT32, 3, ytPtr, dims, str, box, es,
            CU_TENSOR_MAP_INTERLEAVE_NONE, CU_TENSOR_MAP_SWIZZLE_128B,
            CU_TENSOR_MAP_L2_PROMOTION_L2_128B, CU_TENSOR_MAP_FLOAT_OOB_FILL_NONE);
    }

    cudaFuncSetAttribute(gcn_main, cudaFuncAttributeMaxDynamicSharedMemorySize, SMEM_TOTAL);

    y_kernel<<<NN / 128, 128>>>(X, Wg);
    gcn_main<<<NN / MTILE, 256, SMEM_TOTAL>>>(tmA, tmB, X, wv, out);
}

// round 13
// speedup vs baseline: 2.2273x; 1.4204x over previous
#include <cuda_runtime.h>
#include <cuda.h>
#include <cuda_bf16.h>
#include <cstdint>
#include <cstddef>

// Problem dims
#define NN 16384
#define DD 64
#define MTILE 128
#define KTILE 128
#define NKT (NN / KTILE)            // 128 k-tiles

// Smem: A fp32 tile 4 chunk-tiles [128 x 128B] (SW128), B bf16 2 chunk-tiles [64 x 128B]
#define A_TILE_B 65536
#define B_TILE_B 16384
#define STAGE_B (A_TILE_B + B_TILE_B)       // 81920
#define ABF_B 32768                         // A bf16: 2 chunk-tiles [128 x 128B]
#define CTRL_B 1024
#define SMEM_TOTAL (CTRL_B + 2 * STAGE_B + ABF_B)   // 197632
#define TX_BYTES STAGE_B

// Scratch: Y^T = (X @ W_agg)^T as bf16, [DD][NN], K-major
__device__ __nv_bfloat16 g_Yt[(size_t)DD * NN];

// ---------------- helpers ----------------
__device__ __forceinline__ uint32_t smem_u32(const void* p) {
    uint32_t a;
    asm("{ .reg .u64 t; cvta.to.shared.u64 t, %1; cvt.u32.u64 %0, t; }" : "=r"(a) : "l"(p));
    return a;
}
#define MBAR_INIT(a, c) \
    asm volatile("mbarrier.init.shared.b64 [%0], %1;" :: "r"(a), "r"(c) : "memory")
#define MBAR_EXPECT(a, b) \
    asm volatile("mbarrier.arrive.expect_tx.shared.b64 _, [%0], %1;" :: "r"(a), "r"(b) : "memory")

__device__ __forceinline__ void mbar_wait(uint32_t mbar, uint32_t parity) {
    asm volatile(
        "{\n\t.reg .pred P;\n"
        "W_%=:\n\t"
        "mbarrier.try_wait.parity.acquire.cta.shared::cta.b64 P, [%0], %1, 0x989680;\n\t"
        "@P bra.uni D_%=;\n\t"
        "bra.uni W_%=;\n"
        "D_%=:\n\t}"
        :: "r"(mbar), "r"(parity) : "memory");
}

__device__ __forceinline__ void tma3(uint32_t dst, const CUtensorMap* tm,
                                     int x, int y, int z, uint32_t mbar) {
    asm volatile(
        "cp.async.bulk.tensor.3d.shared::cta.global.tile.mbarrier::complete_tx::bytes "
        "[%0], [%1, {%2, %3, %4}], [%5];"
        :: "r"(dst), "l"(tm), "r"(x), "r"(y), "r"(z), "r"(mbar) : "memory");
}

__device__ __forceinline__ void ldsm_x4(uint32_t r[4], uint32_t addr) {
    asm volatile("ldmatrix.sync.aligned.m8n8.x4.shared.b16 {%0,%1,%2,%3}, [%4];"
                 : "=r"(r[0]), "=r"(r[1]), "=r"(r[2]), "=r"(r[3]) : "r"(addr));
}

// bf16 mma.sync m16n8k16, row.col, f32 accumulate
__device__ __forceinline__ void mma_bf16(float d[4], const uint32_t a[4],
                                         uint32_t b0, uint32_t b1) {
    asm volatile(
        "mma.sync.aligned.m16n8k16.row.col.f32.bf16.bf16.f32 "
        "{%0,%1,%2,%3}, {%4,%5,%6,%7}, {%8,%9}, {%0,%1,%2,%3};"
        : "+f"(d[0]), "+f"(d[1]), "+f"(d[2]), "+f"(d[3])
        : "r"(a[0]), "r"(a[1]), "r"(a[2]), "r"(a[3]), "r"(b0), "r"(b1));
}

// pack {lo, hi} floats -> bf16x2 (rn)
__device__ __forceinline__ uint32_t cvt2(float lo, float hi) {
    uint32_t d;
    asm("cvt.rn.bf16x2.f32 %0, %1, %2;" : "=r"(d) : "f"(hi), "f"(lo));
    return d;
}

// ---------------- Kernel 1: Yt = bf16( (X @ W_agg)^T ) ----------------
__global__ void __launch_bounds__(128) y_kernel(const float* __restrict__ X,
                                                const float* __restrict__ Wg) {
    __shared__ float Ws[DD * DD];
    const int t = threadIdx.x;
    for (int i = t; i < DD * DD; i += 128) Ws[i] = Wg[i];
    __syncthreads();

    const int row = blockIdx.x * 128 + t;
    float4 xv[16];
    const float4* Xr = (const float4*)(X + (size_t)row * DD);
#pragma unroll
    for (int i = 0; i < 16; ++i) xv[i] = Xr[i];
    const float* xs = (const float*)xv;

#pragma unroll
    for (int p = 0; p < 4; ++p) {
        float acc[16];
#pragma unroll
        for (int d = 0; d < 16; ++d) acc[d] = 0.f;
#pragma unroll
        for (int j = 0; j < 64; ++j) {
            const float xj = xs[j];
            const float4* wr = (const float4*)&Ws[j * 64 + p * 16];
            float4 w0 = wr[0], w1 = wr[1], w2 = wr[2], w3 = wr[3];
            acc[0]  += xj * w0.x; acc[1]  += xj * w0.y; acc[2]  += xj * w0.z; acc[3]  += xj * w0.w;
            acc[4]  += xj * w1.x; acc[5]  += xj * w1.y; acc[6]  += xj * w1.z; acc[7]  += xj * w1.w;
            acc[8]  += xj * w2.x; acc[9]  += xj * w2.y; acc[10] += xj * w2.z; acc[11] += xj * w2.w;
            acc[12] += xj * w3.x; acc[13] += xj * w3.y; acc[14] += xj * w3.z; acc[15] += xj * w3.w;
        }
#pragma unroll
        for (int d = 0; d < 16; ++d)
            g_Yt[(size_t)(p * 16 + d) * NN + row] = __float2bfloat16_rn(acc[d]);
    }
}

// ---------------- Kernel 2: main GEMM (TMA fill, bf16 mma) + fused epilogue ----------------
__device__ __forceinline__ void fill_stage(uint32_t sb, int slot, int kt,
                                           const CUtensorMap* tmA, const CUtensorMap* tmB,
                                           int mbase, int tid) {
    if (tid == 0) {
        const uint32_t mbar = sb + 8 * slot;
        const uint32_t st = sb + CTRL_B + slot * STAGE_B;
        MBAR_EXPECT(mbar, TX_BYTES);
        tma3(st, tmA, 0, mbase, kt * 4, mbar);              // A fp32 128x128f (64KB)
        tma3(st + A_TILE_B, tmB, 0, 0, kt * 2, mbar);       // B bf16 64x128 (16KB)
    }
}

__global__ void __launch_bounds__(256, 1) gcn_main(
    const __grid_constant__ CUtensorMap tmA,
    const __grid_constant__ CUtensorMap tmB,
    const float* __restrict__ X,
    const float* __restrict__ wv,
    float* __restrict__ out) {
    extern __shared__ __align__(1024) float smem[];
    const uint32_t sb = smem_u32(smem);
    const int tid = threadIdx.x;
    const int lane = tid & 31;
    const int wid = tid >> 5;
    const int wm = wid & 3;        // 4 m-groups of 32 rows
    const int wn = wid >> 2;       // 2 n-groups of 32 cols
    const int mbase = blockIdx.x * MTILE;
    const uint32_t sAbf = sb + CTRL_B + 2 * STAGE_B;

    if (tid == 0) {
        MBAR_INIT(sb + 0, 1);
        MBAR_INIT(sb + 8, 1);
    }
    __syncthreads();

    float acc[2][4][4];
#pragma unroll
    for (int ms = 0; ms < 2; ++ms)
#pragma unroll
        for (int ns = 0; ns < 4; ++ns)
#pragma unroll
            for (int r = 0; r < 4; ++r) acc[ms][ns][r] = 0.f;

    // cvt-pass constants: thread handles row r, 64-col half h
    const int ch = tid >> 7;            // 0/1 (uniform per warp)
    const int cr = tid & 127;
    const uint32_t cswr = (uint32_t)(cr & 7) << 4;

    // fragment addressing constants (swizzle XOR shared: row&7 == lane&7 for both A and B)
    const uint32_t swx = (uint32_t)(lane & 7) << 4;
    const uint32_t aRow0 = (uint32_t)(wm * 32 + (lane & 15));          // + ms*16
    const uint32_t aColB = (uint32_t)((lane >> 4) << 4);
    const uint32_t bRow0 = (uint32_t)(wn * 32 + (lane & 7) + ((lane >> 4) << 3));  // + half*16
    const uint32_t bColB = (uint32_t)(((lane >> 3) & 1) << 4);

    fill_stage(sb, 0, 0, &tmA, &tmB, mbase, tid);

    int slot = 0;
    for (int kt = 0; kt < NKT; ++kt) {
        mbar_wait(sb + 8 * slot, (kt >> 1) & 1);
        __syncthreads();   // all warps done with stage slot^1 AND Abf from last iter

        if (kt + 1 < NKT) fill_stage(sb, slot ^ 1, kt + 1, &tmA, &tmB, mbase, tid);

        const uint32_t sA = sb + CTRL_B + slot * STAGE_B;
        const uint32_t sB = sA + A_TILE_B;

        // --- cvt pass: A fp32 (SW128 chunked) -> Abf bf16 (SW128 chunked) ---
        {
            const uint32_t srcb = sA + (uint32_t)(2 * ch) * 16384 + (uint32_t)cr * 128;
            const uint32_t dstb = sAbf + (uint32_t)ch * 16384 + (uint32_t)cr * 128;
#pragma unroll
            for (int s = 0; s < 8; ++s) {
                const uint32_t cbase = srcb + (uint32_t)((s >> 2) * 16384);
                const uint32_t off = (uint32_t)((s & 3) * 32);
                float ax, ay, az, aw, bx, by, bz, bw;
                asm volatile("ld.shared.v4.f32 {%0,%1,%2,%3}, [%4];"
                             : "=f"(ax), "=f"(ay), "=f"(az), "=f"(aw)
                             : "r"(cbase + (off ^ cswr)));
                asm volatile("ld.shared.v4.f32 {%0,%1,%2,%3}, [%4];"
                             : "=f"(bx), "=f"(by), "=f"(bz), "=f"(bw)
                             : "r"(cbase + ((off | 16u) ^ cswr)));
                const uint32_t p0 = cvt2(ax, ay), p1 = cvt2(az, aw);
                const uint32_t p2 = cvt2(bx, by), p3 = cvt2(bz, bw);
                asm volatile("st.shared.v4.b32 [%0], {%1,%2,%3,%4};"
                             :: "r"(dstb + (((uint32_t)(16 * s)) ^ cswr)),
                                "r"(p0), "r"(p1), "r"(p2), "r"(p3) : "memory");
            }
        }
        __syncthreads();   // Abf visible to all warps

        // --- MMA over bf16 A (Abf) and bf16 B (sB) ---
        auto aAddr = [&](int ms, int ks) -> uint32_t {
            return sAbf + (uint32_t)((ks >> 2) * 16384) + (aRow0 + ms * 16) * 128
                   + ((((uint32_t)((ks & 3) * 32)) | aColB) ^ swx);
        };
        auto bAddr = [&](int half, int ks) -> uint32_t {
            return sB + (uint32_t)((ks >> 2) * 8192) + (bRow0 + half * 16) * 128
                   + ((((uint32_t)((ks & 3) * 32)) | bColB) ^ swx);
        };

        uint32_t af[2][2][4], bf[2][2][4];
        ldsm_x4(af[0][0], aAddr(0, 0));
        ldsm_x4(af[0][1], aAddr(1, 0));
        ldsm_x4(bf[0][0], bAddr(0, 0));
        ldsm_x4(bf[0][1], bAddr(1, 0));
#pragma unroll
        for (int ks = 0; ks < 8; ++ks) {       // 8 k16-steps
            const int cur = ks & 1;
            const int nxt = cur ^ 1;
            if (ks + 1 < 8) {
                ldsm_x4(af[nxt][0], aAddr(0, ks + 1));
                ldsm_x4(af[nxt][1], aAddr(1, ks + 1));
                ldsm_x4(bf[nxt][0], bAddr(0, ks + 1));
                ldsm_x4(bf[nxt][1], bAddr(1, ks + 1));
            }
#pragma unroll
            for (int ms = 0; ms < 2; ++ms) {
                mma_bf16(acc[ms][0], af[cur][ms], bf[cur][0][0], bf[cur][0][1]);
                mma_bf16(acc[ms][1], af[cur][ms], bf[cur][0][2], bf[cur][0][3]);
                mma_bf16(acc[ms][2], af[cur][ms], bf[cur][1][0], bf[cur][1][1]);
                mma_bf16(acc[ms][3], af[cur][ms], bf[cur][1][2], bf[cur][1][3]);
            }
        }
        slot ^= 1;
    }

    // Fused epilogue: out = w*relu(acc) + (1-w)*X  (acc layout identical to tf32 path)
    const int l4 = lane >> 2;
    const int lm = lane & 3;
#pragma unroll
    for (int ms = 0; ms < 2; ++ms) {
        const int r0 = mbase + wm * 32 + ms * 16 + l4;
        const int r1 = r0 + 8;
        const float w0 = wv[r0], o0 = 1.0f - w0;
        const float w1 = wv[r1], o1 = 1.0f - w1;
#pragma unroll
        for (int ns = 0; ns < 4; ++ns) {
            const int col = wn * 32 + ns * 8 + lm * 2;
            const float2 x0 = *(const float2*)(X + (size_t)r0 * DD + col);
            const float2 x1 = *(const float2*)(X + (size_t)r1 * DD + col);
            float2 v0, v1;
            v0.x = w0 * fmaxf(acc[ms][ns][0], 0.f) + o0 * x0.x;
            v0.y = w0 * fmaxf(acc[ms][ns][1], 0.f) + o0 * x0.y;
            v1.x = w1 * fmaxf(acc[ms][ns][2], 0.f) + o1 * x1.x;
            v1.y = w1 * fmaxf(acc[ms][ns][3], 0.f) + o1 * x1.y;
            *(float2*)(out + (size_t)r0 * DD + col) = v0;
            *(float2*)(out + (size_t)r1 * DD + col) = v1;
        }
    }
}

// ---------------- launch ----------------
typedef CUresult (*EncodeFn)(CUtensorMap*, CUtensorMapDataType, cuuint32_t, void*,
                             const cuuint64_t*, const cuuint64_t*, const cuuint32_t*,
                             const cuuint32_t*, CUtensorMapInterleave, CUtensorMapSwizzle,
                             CUtensorMapL2promotion, CUtensorMapFloatOOBfill);

extern "C" void kernel_launch(void* const* d_in, const int* in_sizes, int n_in,
                              void* d_out, int out_size) {
    const float* X  = (const float*)d_in[0];
    const float* A  = (const float*)d_in[1];
    const float* wv = (const float*)d_in[2];
    const float* Wg = (const float*)d_in[3];
    float* out = (float*)d_out;

    void* fn = nullptr;
    cudaDriverEntryPointQueryResult qr;
    cudaGetDriverEntryPoint("cuTensorMapEncodeTiled", &fn, cudaEnableDefault, &qr);
    EncodeFn enc = (EncodeFn)fn;

    void* ytPtr = nullptr;
    cudaGetSymbolAddress(&ytPtr, g_Yt);

    CUtensorMap tmA, tmB;
    {   // A fp32 3D: (32 floats, NN rows, chunks); elem (x,y,z) at y*NN*4 + z*128 + x*4
        cuuint64_t dims[3] = {32, NN, NN / 32};
        cuuint64_t str[2]  = {(cuuint64_t)NN * 4, 128};
        cuuint32_t box[3]  = {32, MTILE, KTILE / 32};
        cuuint32_t es[3]   = {1, 1, 1};
        enc(&tmA, CU_TENSOR_MAP_DATA_TYPE_FLOAT32, 3, (void*)A, dims, str, box, es,
            CU_TENSOR_MAP_INTERLEAVE_NONE, CU_TENSOR_MAP_SWIZZLE_128B,
            CU_TENSOR_MAP_L2_PROMOTION_L2_128B, CU_TENSOR_MAP_FLOAT_OOB_FILL_NONE);
    }
    {   // B bf16 3D: (64 bf16, DD rows, chunks); elem (x,y,z) at y*NN*2 + z*128 + x*2
        cuuint64_t dims[3] = {64, DD, NN / 64};
        cuuint64_t str[2]  = {(cuuint64_t)NN * 2, 128};
        cuuint32_t box[3]  = {64, DD, KTILE / 64};
        cuuint32_t es[3]   = {1, 1, 1};
        enc(&tmB, CU_TENSOR_MAP_DATA_TYPE_BFLOAT16, 3, ytPtr, dims, str, box, es,
            CU_TENSOR_MAP_INTERLEAVE_NONE, CU_TENSOR_MAP_SWIZZLE_128B,
            CU_TENSOR_MAP_L2_PROMOTION_L2_128B, CU_TENSOR_MAP_FLOAT_OOB_FILL_NONE);
    }

    cudaFuncSetAttribute(gcn_main, cudaFuncAttributeMaxDynamicSharedMemorySize, SMEM_TOTAL);

    y_kernel<<<NN / 128, 128>>>(X, Wg);
    gcn_main<<<NN / MTILE, 256, SMEM_TOTAL>>>(tmA, tmB, X, wv, out);
}